// round 6
// baseline (speedup 1.0000x reference)
#include <cuda_runtime.h>
#include <cuda_fp16.h>
#include <cstdint>

// LSTMCell via mma.sync (HMMA) fp16 GEMM, fp32 accum, fused epilogue.
//   P[B,512] = [x|h][B,256] @ B'[512,256]^T,  n = gate*128 + j
// Persistent kernel; warp-specialized: 16 compute warps + 2 producer warps
// that stage A (fp32 gmem -> fp16 smem) for the next tile. One sync/tile.

namespace {

constexpr int Bsz   = 131072;
constexpr int HH    = 128;
constexpr int NWORK = 4096;          // 1024 mtiles * 4 jblocks
constexpr int NTHR  = 576;           // 512 compute + 64 producer

// fp16 weights, K-major: g_B[n][k], n = gate*128 + j, k = 0..255
__device__ __align__(16) __half g_B[512 * 256];

__device__ __forceinline__ uint32_t s2u(const void* p) {
    uint32_t a;
    asm("{ .reg .u64 t; cvta.to.shared.u64 t, %1; cvt.u32.u64 %0, t; }" : "=r"(a) : "l"(p));
    return a;
}
__device__ __forceinline__ float tanh_fast(float v) {
    float r;
    asm("tanh.approx.f32 %0, %1;" : "=f"(r) : "f"(v));
    return r;
}
__device__ __forceinline__ float sig_fast(float v) {
    return fmaf(tanh_fast(0.5f * v), 0.5f, 0.5f);
}
__device__ __forceinline__ void mma16816(float* d, uint32_t a0, uint32_t a1, uint32_t a2, uint32_t a3,
                                         uint32_t b0, uint32_t b1) {
    asm volatile("mma.sync.aligned.m16n8k16.row.col.f32.f16.f16.f32 "
                 "{%0,%1,%2,%3},{%4,%5,%6,%7},{%8,%9},{%0,%1,%2,%3};"
                 : "+f"(d[0]), "+f"(d[1]), "+f"(d[2]), "+f"(d[3])
                 : "r"(a0), "r"(a1), "r"(a2), "r"(a3), "r"(b0), "r"(b1));
}
#define LDSM4(r0, r1, r2, r3, addr) \
    asm volatile("ldmatrix.sync.aligned.m8n8.x4.shared.b16 {%0,%1,%2,%3}, [%4];" \
                 : "=r"(r0), "=r"(r1), "=r"(r2), "=r"(r3) : "r"(addr) : "memory")

// ---------------- prep: weights fp32 -> fp16, transposed to [n][k] ----------------
__global__ void prep_w(const float* __restrict__ Wi, const float* __restrict__ Ui,
                       const float* __restrict__ Wf, const float* __restrict__ Uf,
                       const float* __restrict__ Wg, const float* __restrict__ Ug,
                       const float* __restrict__ Wo, const float* __restrict__ Uo) {
    int t = blockIdx.x * 256 + threadIdx.x;   // 8192 threads
    int n = t >> 4;
    int k0 = (t & 15) * 16;
    int g = n >> 7, j = n & 127;
    const float* W = (g == 0) ? Wi : (g == 1) ? Wf : (g == 2) ? Wg : Wo;
    const float* U = (g == 0) ? Ui : (g == 1) ? Uf : (g == 2) ? Ug : Uo;
    __half tmp[16];
    #pragma unroll
    for (int kk = 0; kk < 16; ++kk) {
        int k = k0 + kk;
        float v = (k < 128) ? W[k * 128 + j] : U[(k - 128) * 128 + j];
        tmp[kk] = __float2half_rn(v);
    }
    reinterpret_cast<uint4*>(&g_B[n * 256 + k0])[0] = reinterpret_cast<uint4*>(tmp)[0];
    reinterpret_cast<uint4*>(&g_B[n * 256 + k0])[1] = reinterpret_cast<uint4*>(tmp)[1];
}

// ---------------- main ----------------
// smem (bytes): A0 @0 (67584), A1 @67584, B @135168 (67584)
constexpr int SM_A1 = 67584;     // 128 rows * 264 halves * 2B
constexpr int SM_B  = 135168;
constexpr int SM_TOT = 202752;

__global__ __launch_bounds__(NTHR, 1)
void lstm_main(const float* __restrict__ x, const float* __restrict__ hp,
               const float* __restrict__ cp,
               const float* __restrict__ bi, const float* __restrict__ bf,
               const float* __restrict__ bg, const float* __restrict__ bo,
               float* __restrict__ out, int grid)
{
    extern __shared__ __align__(16) unsigned char smem[];
    const uint32_t sbase = s2u(smem);
    const uint32_t bs_u  = sbase + SM_B;

    const int tid = threadIdx.x, lane = tid & 31, wid = tid >> 5;
    const int jb = blockIdx.x & 3;

    // B tile (fixed for this CTA): 128 n-rows (4 gates x 32 j) x 256 k fp16
    for (int c = tid; c < 4096; c += NTHR) {
        int nl = c >> 5, seg = c & 31;
        int ng = (nl >> 5) * 128 + jb * 32 + (nl & 31);
        uint32_t dst = bs_u + (uint32_t)(nl * 528 + seg * 16);
        const void* src = (const char*)g_B + (size_t)ng * 512 + (size_t)seg * 16;
        asm volatile("cp.async.cg.shared.global [%0], [%1], 16;" :: "r"(dst), "l"(src) : "memory");
    }
    asm volatile("cp.async.commit_group;" ::: "memory");

    int wi = blockIdx.x;

    // ---------------- producer staging lambda ----------------
    // 64 producer threads (ptid 0..63): 8 lanes per row, 8 rows per pass,
    // 16 passes; per (p,q): 2 LDG.128 fp32 -> 4 cvt -> 1 STS.128 fp16.
    const int ptid = tid - 512;
    auto stage = [&](uint32_t abuf, int mtile) {
        const int rl  = ptid >> 3;          // 0..7
        const int cl8 = (ptid & 7) * 8;     // col base 0..56
        #pragma unroll
        for (int p = 0; p < 16; ++p) {
            const int r = p * 8 + rl;
            const size_t rg = (size_t)mtile * 128 + r;
            #pragma unroll
            for (int q = 0; q < 4; ++q) {
                const int col = q * 64 + cl8;           // 0..252
                const float* src = (col < 128) ? (x + rg * 128 + col)
                                               : (hp + rg * 128 + (col - 128));
                float4 v0 = *(const float4*)src;
                float4 v1 = *(const float4*)(src + 4);
                __half2 h0 = __floats2half2_rn(v0.x, v0.y);
                __half2 h1 = __floats2half2_rn(v0.z, v0.w);
                __half2 h2 = __floats2half2_rn(v1.x, v1.y);
                __half2 h3 = __floats2half2_rn(v1.z, v1.w);
                uint32_t a = abuf + (uint32_t)(r * 528 + col * 2);
                asm volatile("st.shared.v4.b32 [%0], {%1,%2,%3,%4};"
                             :: "r"(a), "r"(*(uint32_t*)&h0), "r"(*(uint32_t*)&h1),
                                "r"(*(uint32_t*)&h2), "r"(*(uint32_t*)&h3) : "memory");
            }
        }
    };

    // warp tiling (compute warps 0..15): wm 0..3 -> rows wm*32; wn 0..3 -> j-slice wn*8
    const int wm = wid & 3, wn = wid >> 2;
    const uint32_t aoff0 = (uint32_t)(((wm * 32 +      (lane & 15)) * 264 + (lane >> 4) * 8) * 2);
    const uint32_t aoff1 = (uint32_t)(((wm * 32 + 16 + (lane & 15)) * 264 + (lane >> 4) * 8) * 2);
    const uint32_t bAddr = bs_u + (uint32_t)(((lane >> 3) * 32 + wn * 8 + (lane & 7)) * 528);

    const int jgl = jb * 32 + wn * 8 + 2 * (lane & 3);
    float2 bI, bF, bG, bO;
    if (tid < 512) {
        bI = *(const float2*)&bi[jgl];
        bF = *(const float2*)&bf[jgl];
        bG = *(const float2*)&bg[jgl];
        bO = *(const float2*)&bo[jgl];
    }

    // prologue: producer stages tile0 into buf0 while cp.async(B) flies
    if (tid >= 512) stage(sbase, wi >> 2);
    asm volatile("cp.async.wait_group 0;" ::: "memory");
    __syncthreads();   // B + A(tile0) visible

    float* out_h = out;
    float* out_c = out + (size_t)Bsz * HH;

    for (int it = 0; wi < NWORK; wi += grid, ++it) {
        const uint32_t abase = sbase + (uint32_t)((it & 1) * SM_A1);

        if (tid < 512) {
            const int mtile = wi >> 2;
            // c_prev prefetch for epilogue
            const int rbase = mtile * 128 + wm * 32 + (lane >> 2);
            float2 cpv[2][2];
            #pragma unroll
            for (int mf = 0; mf < 2; ++mf)
                #pragma unroll
                for (int rr = 0; rr < 2; ++rr)
                    cpv[mf][rr] = *(const float2*)&cp[(size_t)(rbase + mf * 16 + rr * 8) * HH + jgl];

            // ---- MMA mainloop: 16 k-steps; per ks: 2 A-LDSM4 + 2 B-LDSM4, 8 HMMA ----
            float acc[2][4][4];
            #pragma unroll
            for (int mf = 0; mf < 2; ++mf)
                #pragma unroll
                for (int g = 0; g < 4; ++g)
                    #pragma unroll
                    for (int e = 0; e < 4; ++e) acc[mf][g][e] = 0.f;

            #pragma unroll
            for (int ks = 0; ks < 16; ++ks) {
                uint32_t a0, a1, a2, a3, a4, a5, a6, a7;
                LDSM4(a0, a1, a2, a3, abase + aoff0 + ks * 32);
                LDSM4(a4, a5, a6, a7, abase + aoff1 + ks * 32);
                uint32_t p0, p1, p2, p3, q0, q1, q2, q3;
                LDSM4(p0, p1, p2, p3, bAddr + ks * 32);        // gates 0..3, k 0-7
                LDSM4(q0, q1, q2, q3, bAddr + ks * 32 + 16);   // gates 0..3, k 8-15
                mma16816(acc[0][0], a0, a1, a2, a3, p0, q0);
                mma16816(acc[1][0], a4, a5, a6, a7, p0, q0);
                mma16816(acc[0][1], a0, a1, a2, a3, p1, q1);
                mma16816(acc[1][1], a4, a5, a6, a7, p1, q1);
                mma16816(acc[0][2], a0, a1, a2, a3, p2, q2);
                mma16816(acc[1][2], a4, a5, a6, a7, p2, q2);
                mma16816(acc[0][3], a0, a1, a2, a3, p3, q3);
                mma16816(acc[1][3], a4, a5, a6, a7, p3, q3);
            }

            // ---- fused epilogue ----
            #pragma unroll
            for (int mf = 0; mf < 2; ++mf) {
                #pragma unroll
                for (int rr = 0; rr < 2; ++rr) {
                    float2 hv, cv;
                    #pragma unroll
                    for (int e = 0; e < 2; ++e) {
                        const float pi_ = acc[mf][0][rr * 2 + e] + (e ? bI.y : bI.x);
                        const float pf_ = acc[mf][1][rr * 2 + e] + (e ? bF.y : bF.x);
                        const float pg_ = acc[mf][2][rr * 2 + e] + (e ? bG.y : bG.x);
                        const float po_ = acc[mf][3][rr * 2 + e] + (e ? bO.y : bO.x);
                        const float ig = sig_fast(pi_);
                        const float fg = sig_fast(pf_);
                        const float og = sig_fast(po_);
                        const float gg = tanh_fast(pg_);
                        const float cpe = e ? cpv[mf][rr].y : cpv[mf][rr].x;
                        const float cn = fg * cpe + ig * gg;
                        const float hn = og * tanh_fast(cn);
                        if (e) { cv.y = cn; hv.y = hn; } else { cv.x = cn; hv.x = hn; }
                    }
                    const size_t o = (size_t)(rbase + mf * 16 + rr * 8) * HH + jgl;
                    *(float2*)&out_h[o] = hv;
                    *(float2*)&out_c[o] = cv;
                }
            }
        } else {
            // producer: stage next tile's A into the other buffer
            const int win = wi + grid;
            if (win < NWORK)
                stage(sbase + (uint32_t)(((it + 1) & 1) * SM_A1), win >> 2);
        }
        __syncthreads();   // buffer handoff
    }
}

} // namespace

extern "C" void kernel_launch(void* const* d_in, const int* in_sizes, int n_in,
                              void* d_out, int out_size)
{
    (void)in_sizes; (void)n_in; (void)out_size;
    const float* x      = (const float*)d_in[0];
    const float* h_prev = (const float*)d_in[1];
    const float* c_prev = (const float*)d_in[2];
    const float* Wi = (const float*)d_in[3];
    const float* Ui = (const float*)d_in[4];
    const float* bi = (const float*)d_in[5];
    const float* Wf = (const float*)d_in[6];
    const float* Uf = (const float*)d_in[7];
    const float* bf = (const float*)d_in[8];
    const float* Wg = (const float*)d_in[9];
    const float* Ug = (const float*)d_in[10];
    const float* bg = (const float*)d_in[11];
    const float* Wo = (const float*)d_in[12];
    const float* Uo = (const float*)d_in[13];
    const float* bo = (const float*)d_in[14];
    float* out = (float*)d_out;

    int sms = 148;
    cudaDeviceGetAttribute(&sms, cudaDevAttrMultiProcessorCount, 0);
    if (sms < 4 || sms > 1024) sms = 148;
    const int grid = (sms / 4) * 4;   // jb = bid&3 stays fixed per CTA

    cudaFuncSetAttribute(lstm_main, cudaFuncAttributeMaxDynamicSharedMemorySize, SM_TOT);

    prep_w<<<32, 256>>>(Wi, Ui, Wf, Uf, Wg, Ug, Wo, Uo);
    lstm_main<<<grid, NTHR, SM_TOT>>>(x, h_prev, c_prev, bi, bf, bg, bo, out, grid);
}

// round 7
// speedup vs baseline: 1.4632x; 1.4632x over previous
#include <cuda_runtime.h>
#include <cuda_fp16.h>
#include <cstdint>

// LSTMCell via mma.sync (HMMA) fp16 GEMM, fp32 accum, fused epilogue.
//   P[B,512] = [x|h][B,256] @ B'[512,256]^T,  n = gate*128 + j
// prep_a converts [x|h] -> fp16 once; main kernel cp.asyncs A straight to smem
// (no register staging), double-buffered; B tile resident per CTA.

namespace {

constexpr int Bsz   = 131072;
constexpr int HH    = 128;
constexpr int NWORK = 4096;          // 1024 mtiles * 4 jblocks

// fp16 weights, K-major: g_B[n][k], n = gate*128 + j, k = 0..255
__device__ __align__(16) __half g_B[512 * 256];
// fp16 activations: g_A[row][k], row-major, k = 0..255 ([x | h_prev])
__device__ __align__(16) __half g_A[(size_t)Bsz * 256];

__device__ __forceinline__ uint32_t s2u(const void* p) {
    uint32_t a;
    asm("{ .reg .u64 t; cvta.to.shared.u64 t, %1; cvt.u32.u64 %0, t; }" : "=r"(a) : "l"(p));
    return a;
}
__device__ __forceinline__ float tanh_fast(float v) {
    float r;
    asm("tanh.approx.f32 %0, %1;" : "=f"(r) : "f"(v));
    return r;
}
__device__ __forceinline__ float sig_fast(float v) {
    return fmaf(tanh_fast(0.5f * v), 0.5f, 0.5f);
}
__device__ __forceinline__ void mma16816(float* d, uint32_t a0, uint32_t a1, uint32_t a2, uint32_t a3,
                                         uint32_t b0, uint32_t b1) {
    asm volatile("mma.sync.aligned.m16n8k16.row.col.f32.f16.f16.f32 "
                 "{%0,%1,%2,%3},{%4,%5,%6,%7},{%8,%9},{%0,%1,%2,%3};"
                 : "+f"(d[0]), "+f"(d[1]), "+f"(d[2]), "+f"(d[3])
                 : "r"(a0), "r"(a1), "r"(a2), "r"(a3), "r"(b0), "r"(b1));
}
#define LDSM4(r0, r1, r2, r3, addr) \
    asm volatile("ldmatrix.sync.aligned.m8n8.x4.shared.b16 {%0,%1,%2,%3}, [%4];" \
                 : "=r"(r0), "=r"(r1), "=r"(r2), "=r"(r3) : "r"(addr) : "memory")
#define CPASYNC16(dst, src) \
    asm volatile("cp.async.cg.shared.global [%0], [%1], 16;" :: "r"(dst), "l"(src) : "memory")

// ---------------- prep: activations fp32 -> fp16 ----------------
__global__ void prep_a(const float* __restrict__ x, const float* __restrict__ hp) {
    unsigned t = blockIdx.x * 256u + threadIdx.x;   // 4,194,304 threads
    unsigned row = t >> 5;
    unsigned col = (t & 31u) * 8u;
    const float* src = (col < 128) ? (x + (size_t)row * 128 + col)
                                   : (hp + (size_t)row * 128 + (col - 128));
    float4 v0 = *(const float4*)src;
    float4 v1 = *(const float4*)(src + 4);
    __half2 h0 = __floats2half2_rn(v0.x, v0.y);
    __half2 h1 = __floats2half2_rn(v0.z, v0.w);
    __half2 h2 = __floats2half2_rn(v1.x, v1.y);
    __half2 h3 = __floats2half2_rn(v1.z, v1.w);
    uint4 o = make_uint4(*(uint32_t*)&h0, *(uint32_t*)&h1, *(uint32_t*)&h2, *(uint32_t*)&h3);
    *reinterpret_cast<uint4*>(&g_A[(size_t)row * 256 + col]) = o;
}

// ---------------- prep: weights fp32 -> fp16, transposed to [n][k] ----------------
__global__ void prep_w(const float* __restrict__ Wi, const float* __restrict__ Ui,
                       const float* __restrict__ Wf, const float* __restrict__ Uf,
                       const float* __restrict__ Wg, const float* __restrict__ Ug,
                       const float* __restrict__ Wo, const float* __restrict__ Uo) {
    int t = blockIdx.x * 256 + threadIdx.x;   // 8192 threads
    int n = t >> 4;
    int k0 = (t & 15) * 16;
    int g = n >> 7, j = n & 127;
    const float* W = (g == 0) ? Wi : (g == 1) ? Wf : (g == 2) ? Wg : Wo;
    const float* U = (g == 0) ? Ui : (g == 1) ? Uf : (g == 2) ? Ug : Uo;
    __half tmp[16];
    #pragma unroll
    for (int kk = 0; kk < 16; ++kk) {
        int k = k0 + kk;
        float v = (k < 128) ? W[k * 128 + j] : U[(k - 128) * 128 + j];
        tmp[kk] = __float2half_rn(v);
    }
    reinterpret_cast<uint4*>(&g_B[n * 256 + k0])[0] = reinterpret_cast<uint4*>(tmp)[0];
    reinterpret_cast<uint4*>(&g_B[n * 256 + k0])[1] = reinterpret_cast<uint4*>(tmp)[1];
}

// ---------------- main ----------------
// smem (bytes): A0 @0 (67584), A1 @67584, B @135168 (67584)
constexpr int SM_A1 = 67584;     // 128 rows * 264 halves * 2B
constexpr int SM_B  = 135168;
constexpr int SM_TOT = 202752;

__global__ __launch_bounds__(512, 1)
void lstm_main(const float* __restrict__ cp,
               const float* __restrict__ bi, const float* __restrict__ bf,
               const float* __restrict__ bg, const float* __restrict__ bo,
               float* __restrict__ out, int grid)
{
    extern __shared__ __align__(16) unsigned char smem[];
    const uint32_t sbase = s2u(smem);
    const uint32_t bs_u  = sbase + SM_B;

    const int tid = threadIdx.x, lane = tid & 31, wid = tid >> 5;
    const int jb = blockIdx.x & 3;

    // A stage: 8 x 16B cp.async per thread, no RF involvement
    auto issueA = [&](uint32_t abuf, int mtile) {
        #pragma unroll
        for (int i = 0; i < 8; ++i) {
            int c = i * 512 + tid;
            int r = c >> 5, seg = c & 31;
            uint32_t dst = abuf + (uint32_t)(r * 528 + seg * 16);
            const void* src = (const char*)g_A + (size_t)(mtile * 128 + r) * 512 + (size_t)seg * 16;
            CPASYNC16(dst, src);
        }
        asm volatile("cp.async.commit_group;" ::: "memory");
    };

    // B tile (fixed for this CTA): 128 n-rows (4 gates x 32 j) x 256 k fp16
    #pragma unroll
    for (int i = 0; i < 8; ++i) {
        int c  = i * 512 + tid;
        int nl = c >> 5, seg = c & 31;
        int ng = (nl >> 5) * 128 + jb * 32 + (nl & 31);
        uint32_t dst = bs_u + (uint32_t)(nl * 528 + seg * 16);
        const void* src = (const char*)g_B + (size_t)ng * 512 + (size_t)seg * 16;
        CPASYNC16(dst, src);
    }
    int wi = blockIdx.x;
    issueA(sbase, wi >> 2);                                   // group0: B + A(it0)
    if (wi + grid < NWORK) issueA(sbase + SM_A1, (wi + grid) >> 2);
    else asm volatile("cp.async.commit_group;" ::: "memory"); // group1: A(it1)

    // warp tiling: wm 0..3 -> rows wm*32; wn 0..3 -> j-slice wn*8
    const int wm = wid & 3, wn = wid >> 2;
    const uint32_t aoff0 = (uint32_t)(((wm * 32 +      (lane & 15)) * 264 + (lane >> 4) * 8) * 2);
    const uint32_t aoff1 = (uint32_t)(((wm * 32 + 16 + (lane & 15)) * 264 + (lane >> 4) * 8) * 2);
    const uint32_t bAddr = bs_u + (uint32_t)(((lane >> 3) * 32 + wn * 8 + (lane & 7)) * 528);

    const int jgl = jb * 32 + wn * 8 + 2 * (lane & 3);
    const float2 bI = *(const float2*)&bi[jgl];
    const float2 bF = *(const float2*)&bf[jgl];
    const float2 bG = *(const float2*)&bg[jgl];
    const float2 bO = *(const float2*)&bo[jgl];

    asm volatile("cp.async.wait_group 1;" ::: "memory");      // B + A(it0) landed
    __syncthreads();

    float* out_h = out;
    float* out_c = out + (size_t)Bsz * HH;

    for (int it = 0; wi < NWORK; wi += grid, ++it) {
        const int mtile = wi >> 2;
        const uint32_t abase = sbase + (uint32_t)((it & 1) * SM_A1);

        // c_prev prefetch for epilogue
        const int rbase = mtile * 128 + wm * 32 + (lane >> 2);
        float2 cpv[2][2];
        #pragma unroll
        for (int mf = 0; mf < 2; ++mf)
            #pragma unroll
            for (int rr = 0; rr < 2; ++rr)
                cpv[mf][rr] = *(const float2*)&cp[(size_t)(rbase + mf * 16 + rr * 8) * HH + jgl];

        // ---- MMA mainloop: 16 k-steps; per ks: 2 A-LDSM4 + 2 B-LDSM4, 8 HMMA ----
        float acc[2][4][4];   // [mfrag][gate][elem]
        #pragma unroll
        for (int mf = 0; mf < 2; ++mf)
            #pragma unroll
            for (int g = 0; g < 4; ++g)
                #pragma unroll
                for (int e = 0; e < 4; ++e) acc[mf][g][e] = 0.f;

        #pragma unroll
        for (int ks = 0; ks < 16; ++ks) {
            uint32_t a0, a1, a2, a3, a4, a5, a6, a7;
            LDSM4(a0, a1, a2, a3, abase + aoff0 + ks * 32);
            LDSM4(a4, a5, a6, a7, abase + aoff1 + ks * 32);
            uint32_t p0, p1, p2, p3, q0, q1, q2, q3;
            LDSM4(p0, p1, p2, p3, bAddr + ks * 32);        // gates 0..3, k 0-7
            LDSM4(q0, q1, q2, q3, bAddr + ks * 32 + 16);   // gates 0..3, k 8-15
            mma16816(acc[0][0], a0, a1, a2, a3, p0, q0);
            mma16816(acc[1][0], a4, a5, a6, a7, p0, q0);
            mma16816(acc[0][1], a0, a1, a2, a3, p1, q1);
            mma16816(acc[1][1], a4, a5, a6, a7, p1, q1);
            mma16816(acc[0][2], a0, a1, a2, a3, p2, q2);
            mma16816(acc[1][2], a4, a5, a6, a7, p2, q2);
            mma16816(acc[0][3], a0, a1, a2, a3, p3, q3);
            mma16816(acc[1][3], a4, a5, a6, a7, p3, q3);
        }

        // ---- fused epilogue ----
        #pragma unroll
        for (int mf = 0; mf < 2; ++mf) {
            #pragma unroll
            for (int rr = 0; rr < 2; ++rr) {
                float2 hv, cv;
                #pragma unroll
                for (int e = 0; e < 2; ++e) {
                    const float pi_ = acc[mf][0][rr * 2 + e] + (e ? bI.y : bI.x);
                    const float pf_ = acc[mf][1][rr * 2 + e] + (e ? bF.y : bF.x);
                    const float pg_ = acc[mf][2][rr * 2 + e] + (e ? bG.y : bG.x);
                    const float po_ = acc[mf][3][rr * 2 + e] + (e ? bO.y : bO.x);
                    const float ig = sig_fast(pi_);
                    const float fg = sig_fast(pf_);
                    const float og = sig_fast(po_);
                    const float gg = tanh_fast(pg_);
                    const float cpe = e ? cpv[mf][rr].y : cpv[mf][rr].x;
                    const float cn = fg * cpe + ig * gg;
                    const float hn = og * tanh_fast(cn);
                    if (e) { cv.y = cn; hv.y = hn; } else { cv.x = cn; hv.x = hn; }
                }
                const size_t o = (size_t)(rbase + mf * 16 + rr * 8) * HH + jgl;
                *(float2*)&out_h[o] = hv;
                *(float2*)&out_c[o] = cv;
            }
        }

        // ---- refill the buffer just consumed with A(it+2) ----
        __syncthreads();                                  // everyone done reading abase
        const int w2 = wi + 2 * grid;
        if (w2 < NWORK) issueA(abase, w2 >> 2);
        else asm volatile("cp.async.commit_group;" ::: "memory");
        asm volatile("cp.async.wait_group 1;" ::: "memory");  // A(it+1) ready
        __syncthreads();
    }
}

} // namespace

extern "C" void kernel_launch(void* const* d_in, const int* in_sizes, int n_in,
                              void* d_out, int out_size)
{
    (void)in_sizes; (void)n_in; (void)out_size;
    const float* x      = (const float*)d_in[0];
    const float* h_prev = (const float*)d_in[1];
    const float* c_prev = (const float*)d_in[2];
    const float* Wi = (const float*)d_in[3];
    const float* Ui = (const float*)d_in[4];
    const float* bi = (const float*)d_in[5];
    const float* Wf = (const float*)d_in[6];
    const float* Uf = (const float*)d_in[7];
    const float* bf = (const float*)d_in[8];
    const float* Wg = (const float*)d_in[9];
    const float* Ug = (const float*)d_in[10];
    const float* bg = (const float*)d_in[11];
    const float* Wo = (const float*)d_in[12];
    const float* Uo = (const float*)d_in[13];
    const float* bo = (const float*)d_in[14];
    float* out = (float*)d_out;

    int sms = 148;
    cudaDeviceGetAttribute(&sms, cudaDevAttrMultiProcessorCount, 0);
    if (sms < 4 || sms > 1024) sms = 148;
    const int grid = (sms / 4) * 4;   // jb = bid&3 stays fixed per CTA

    cudaFuncSetAttribute(lstm_main, cudaFuncAttributeMaxDynamicSharedMemorySize, SM_TOT);

    prep_a<<<16384, 256>>>(x, h_prev);
    prep_w<<<32, 256>>>(Wi, Ui, Wf, Uf, Wg, Ug, Wo, Uo);
    lstm_main<<<grid, 512, SM_TOT>>>(c_prev, bi, bf, bg, bo, out, grid);
}